// round 1
// baseline (speedup 1.0000x reference)
#include <cuda_runtime.h>
#include <cstdint>

#define SEQ   2048
#define BATCH 32
#define IDIM  256
#define HDIM  256
#define G4    1024   // 4*HDIM gate rows

// 268 MB scratch for precomputed input projections: Xg[t][b][g] (g in 0..1023)
__device__ float g_xg[SEQ * BATCH * G4];

// ---------------------------------------------------------------------------
// Kernel 1: Xg[m][n] = sum_k x[m][k] * W_ih[n][k] + b_ih[n] + b_hh[n]
//           m = t*BATCH + b  (65536 rows), n = gate row (1024 cols), K = 256
// Tiled fp32 SGEMM: 64x64 tile, BK=32, 256 threads, 4x4 microtile.
// ---------------------------------------------------------------------------
#define BM 64
#define BN 64
#define BK 32

__global__ __launch_bounds__(256) void xproj_kernel(
    const float* __restrict__ x,
    const float* __restrict__ Wih,
    const float* __restrict__ bih,
    const float* __restrict__ bhh)
{
    __shared__ float As[BK][BM];
    __shared__ float Bs[BK][BN];

    const int tid  = threadIdx.x;
    const int mblk = blockIdx.x;   // 0..1023
    const int nblk = blockIdx.y;   // 0..15

    const float* Arow = x   + (size_t)mblk * BM * IDIM;
    const float* Brow = Wih + (size_t)nblk * BN * IDIM;

    const int tx = tid & 15;
    const int ty = tid >> 4;

    float acc[4][4] = {};

    const int lr  = tid >> 2;        // 0..63 row within tile for loads
    const int lkq = (tid & 3) * 8;   // 0,8,16,24 k-offset for loads

    for (int k0 = 0; k0 < IDIM; k0 += BK) {
        // load A tile (64 x 32) transposed into As[k][m]
        {
            float4 v0 = *(const float4*)(Arow + lr * IDIM + k0 + lkq);
            float4 v1 = *(const float4*)(Arow + lr * IDIM + k0 + lkq + 4);
            As[lkq + 0][lr] = v0.x; As[lkq + 1][lr] = v0.y;
            As[lkq + 2][lr] = v0.z; As[lkq + 3][lr] = v0.w;
            As[lkq + 4][lr] = v1.x; As[lkq + 5][lr] = v1.y;
            As[lkq + 6][lr] = v1.z; As[lkq + 7][lr] = v1.w;

            float4 w0 = *(const float4*)(Brow + lr * IDIM + k0 + lkq);
            float4 w1 = *(const float4*)(Brow + lr * IDIM + k0 + lkq + 4);
            Bs[lkq + 0][lr] = w0.x; Bs[lkq + 1][lr] = w0.y;
            Bs[lkq + 2][lr] = w0.z; Bs[lkq + 3][lr] = w0.w;
            Bs[lkq + 4][lr] = w1.x; Bs[lkq + 5][lr] = w1.y;
            Bs[lkq + 6][lr] = w1.z; Bs[lkq + 7][lr] = w1.w;
        }
        __syncthreads();

        #pragma unroll
        for (int kk = 0; kk < BK; kk++) {
            float4 av = *(const float4*)&As[kk][ty * 4];
            float4 bv = *(const float4*)&Bs[kk][tx * 4];
            float a[4] = {av.x, av.y, av.z, av.w};
            float b[4] = {bv.x, bv.y, bv.z, bv.w};
            #pragma unroll
            for (int i = 0; i < 4; i++)
                #pragma unroll
                for (int j = 0; j < 4; j++)
                    acc[i][j] = fmaf(a[i], b[j], acc[i][j]);
        }
        __syncthreads();
    }

    // epilogue: add fused bias, store
    const int mb = mblk * BM + ty * 4;
    const int nb = nblk * BN + tx * 4;
    float bias[4];
    #pragma unroll
    for (int j = 0; j < 4; j++)
        bias[j] = bih[nb + j] + bhh[nb + j];

    #pragma unroll
    for (int i = 0; i < 4; i++) {
        float4 v;
        v.x = acc[i][0] + bias[0];
        v.y = acc[i][1] + bias[1];
        v.z = acc[i][2] + bias[2];
        v.w = acc[i][3] + bias[3];
        *(float4*)&g_xg[(size_t)(mb + i) * G4 + nb] = v;
    }
}

// ---------------------------------------------------------------------------
// Kernel 2: the sequential recurrence.
// 16 clusters of 8 CTAs; each cluster owns 2 batches. CTA rank owns 32 hidden
// units (= 128 gate rows), W_hh slice lives in registers (128 floats/thread).
// Per step: gates = Xg[t] + W_hh @ h ; activations ; h broadcast to the 8
// peer CTAs via st.shared::cluster ; one cluster barrier.
// Thread map (256 threads): warp w -> kseg = w>>1 (64-wide K segment),
// half = w&1; g_idx = half*32+lane in 0..63; thread computes rows
// {2*g_idx, 2*g_idx+1} x 2 batches over its K segment.
// ---------------------------------------------------------------------------
__global__ void __cluster_dims__(8, 1, 1) __launch_bounds__(256, 1)
lstm_rec_kernel(const float* __restrict__ Whh,
                const float* __restrict__ h0,
                const float* __restrict__ c0,
                float* __restrict__ out)
{
    __shared__ float h_s[2][2][HDIM];      // [buf][local batch][k]
    __shared__ float red_s[4][64][4];      // [kseg][g_idx][{r0b0,r0b1,r1b0,r1b1}]
    __shared__ float gates_s[2][128];      // [local batch][gate*32 + j_local]

    const int tid  = threadIdx.x;
    const int lane = tid & 31;
    const int w    = tid >> 5;
    const int kseg = w >> 1;               // 0..3
    const int half = w & 1;
    const int g_idx = half * 32 + lane;    // 0..63

    unsigned rank;
    asm("mov.u32 %0, %%cluster_ctarank;" : "=r"(rank));
    const int cl = blockIdx.x >> 3;        // cluster id 0..15
    const int b0 = cl * 2;                 // first global batch of this cluster

    // this thread's two gate rows (local rows 2*g_idx, 2*g_idx+1 of the CTA's
    // 128-row list: local row lr -> gate = lr>>5, j = lr&31,
    // global W row = gate*256 + rank*32 + j)
    const int lr0 = 2 * g_idx;
    const int lr1 = lr0 + 1;
    const int R0  = ((lr0 >> 5) << 8) + (int)rank * 32 + (lr0 & 31);
    const int R1  = ((lr1 >> 5) << 8) + (int)rank * 32 + (lr1 & 31);

    // ---- preload W_hh slice into registers (128 floats/thread) ----
    float wreg0[64], wreg1[64];
    {
        const float* W0 = Whh + (size_t)R0 * HDIM + kseg * 64;
        const float* W1 = Whh + (size_t)R1 * HDIM + kseg * 64;
        #pragma unroll
        for (int i = 0; i < 16; i++) {
            float4 a = *(const float4*)(W0 + 4 * i);
            wreg0[4*i+0] = a.x; wreg0[4*i+1] = a.y; wreg0[4*i+2] = a.z; wreg0[4*i+3] = a.w;
            float4 b = *(const float4*)(W1 + 4 * i);
            wreg1[4*i+0] = b.x; wreg1[4*i+1] = b.y; wreg1[4*i+2] = b.z; wreg1[4*i+3] = b.w;
        }
    }

    // ---- init h_s[0] with h0 for both local batches ----
    for (int i = tid; i < 2 * HDIM; i += 256) {
        int bb = i >> 8;
        int k  = i & 255;
        h_s[0][bb][k] = h0[(size_t)(b0 + bb) * HDIM + k];
    }

    // ---- c state: threads 0..63 each own one (bb, j) cell ----
    float c_reg = 0.f;
    if (tid < 64) {
        int bb = tid >> 5, j = tid & 31;
        c_reg = c0[(size_t)(b0 + bb) * HDIM + (int)rank * 32 + j];
    }
    __syncthreads();

    // reduction-phase output mapping: thread -> (lrO, bbO)
    const int lrO = tid >> 1;
    const int bbO = tid & 1;
    const int RO  = ((lrO >> 5) << 8) + (int)rank * 32 + (lrO & 31);

    float* const ysOut = out;
    float* const hTOut = out + (size_t)SEQ * BATCH * HDIM;
    float* const cTOut = hTOut + (size_t)BATCH * HDIM;

    int p = 0;
    for (int t = SEQ - 1; t >= 0; t--) {
        // prefetch this step's input-projection value (consumed after k-loop)
        const float xg = g_xg[((size_t)t * BATCH + b0 + bbO) * G4 + RO];

        // ---- k-loop: 64 K values, 2 rows x 2 batches, W in registers ----
        float a00 = 0.f, a01 = 0.f, a10 = 0.f, a11 = 0.f;
        const float* hp0 = &h_s[p][0][kseg * 64];
        const float* hp1 = &h_s[p][1][kseg * 64];
        #pragma unroll
        for (int i = 0; i < 64; i += 4) {
            float4 hv0 = *(const float4*)(hp0 + i);
            float4 hv1 = *(const float4*)(hp1 + i);
            a00 = fmaf(wreg0[i+0], hv0.x, a00); a01 = fmaf(wreg0[i+0], hv1.x, a01);
            a10 = fmaf(wreg1[i+0], hv0.x, a10); a11 = fmaf(wreg1[i+0], hv1.x, a11);
            a00 = fmaf(wreg0[i+1], hv0.y, a00); a01 = fmaf(wreg0[i+1], hv1.y, a01);
            a10 = fmaf(wreg1[i+1], hv0.y, a10); a11 = fmaf(wreg1[i+1], hv1.y, a11);
            a00 = fmaf(wreg0[i+2], hv0.z, a00); a01 = fmaf(wreg0[i+2], hv1.z, a01);
            a10 = fmaf(wreg1[i+2], hv0.z, a10); a11 = fmaf(wreg1[i+2], hv1.z, a11);
            a00 = fmaf(wreg0[i+3], hv0.w, a00); a01 = fmaf(wreg0[i+3], hv1.w, a01);
            a10 = fmaf(wreg1[i+3], hv0.w, a10); a11 = fmaf(wreg1[i+3], hv1.w, a11);
        }
        red_s[kseg][g_idx][0] = a00;
        red_s[kseg][g_idx][1] = a01;
        red_s[kseg][g_idx][2] = a10;
        red_s[kseg][g_idx][3] = a11;
        __syncthreads();

        // ---- reduce across the 4 K segments; add xg; stage gate value ----
        {
            const int gi  = lrO >> 1;
            const int idx = ((lrO & 1) << 1) + bbO;
            float s = xg;
            #pragma unroll
            for (int ks2 = 0; ks2 < 4; ks2++)
                s += red_s[ks2][gi][idx];
            gates_s[bbO][lrO] = s;
        }
        __syncthreads();

        // ---- activations + state update + h broadcast (threads 0..63) ----
        if (tid < 64) {
            const int bb = tid >> 5, j = tid & 31;
            const float ig = gates_s[bb][ 0 + j];
            const float fg = gates_s[bb][32 + j];
            const float gg = gates_s[bb][64 + j];
            const float og = gates_s[bb][96 + j];

            const float isig = 1.f / (1.f + __expf(-ig));
            const float fsig = 1.f / (1.f + __expf(-fg));
            const float gt   = tanhf(gg);
            const float osig = 1.f / (1.f + __expf(-og));

            c_reg = fsig * c_reg + isig * gt;
            const float h = osig * tanhf(c_reg);

            // output for this timestep
            ysOut[((size_t)t * BATCH + b0 + bb) * HDIM + (int)rank * 32 + j] = h;

            // broadcast h to all 8 cluster CTAs' h_s[p^1][bb][rank*32+j]
            uint32_t laddr = (uint32_t)__cvta_generic_to_shared(
                &h_s[p ^ 1][bb][(int)rank * 32 + j]);
            #pragma unroll
            for (int r = 0; r < 8; r++) {
                uint32_t raddr;
                asm volatile("mapa.shared::cluster.u32 %0, %1, %2;"
                             : "=r"(raddr) : "r"(laddr), "r"(r));
                asm volatile("st.shared::cluster.f32 [%0], %1;"
                             :: "r"(raddr), "f"(h) : "memory");
            }
        }

        // one cluster barrier per step (release writes / acquire for next read)
        asm volatile("barrier.cluster.arrive.aligned;" ::: "memory");
        asm volatile("barrier.cluster.wait.aligned;" ::: "memory");
        p ^= 1;
    }

    // final carry (state after consuming x[0])
    if (tid < 64) {
        const int bb = tid >> 5, j = tid & 31;
        const float hfin = h_s[p][bb][(int)rank * 32 + j];
        hTOut[(size_t)(b0 + bb) * HDIM + (int)rank * 32 + j] = hfin;
        cTOut[(size_t)(b0 + bb) * HDIM + (int)rank * 32 + j] = c_reg;
    }
}

// ---------------------------------------------------------------------------
extern "C" void kernel_launch(void* const* d_in, const int* in_sizes, int n_in,
                              void* d_out, int out_size)
{
    (void)in_sizes; (void)n_in; (void)out_size;
    const float* x   = (const float*)d_in[0];
    const float* h0  = (const float*)d_in[1];
    const float* c0  = (const float*)d_in[2];
    const float* Wih = (const float*)d_in[3];
    const float* Whh = (const float*)d_in[4];
    const float* bih = (const float*)d_in[5];
    const float* bhh = (const float*)d_in[6];
    float* out = (float*)d_out;

    dim3 gridP(65536 / BM, G4 / BN);   // (1024, 16)
    xproj_kernel<<<gridP, 256>>>(x, Wih, bih, bhh);

    // 16 clusters x 8 CTAs (2 batches per cluster), 256 threads each
    lstm_rec_kernel<<<128, 256>>>(Whh, h0, c0, out);
}

// round 2
// speedup vs baseline: 1.1520x; 1.1520x over previous
#include <cuda_runtime.h>
#include <cstdint>

#define SEQ   2048
#define BATCH 32
#define IDIM  256
#define HDIM  256
#define G4    1024   // 4*HDIM gate rows

// 268 MB scratch for precomputed input projections: Xg[t][b][g]
__device__ float g_xg[SEQ * BATCH * G4];

// ---------------------------------------------------------------------------
// Kernel 1: Xg[m][n] = sum_k x[m][k] * W_ih[n][k] + b_ih[n] + b_hh[n]
// (unchanged control from R0 — known correct; optimize later once the
//  recurrence-vs-xproj split is measured)
// ---------------------------------------------------------------------------
#define BM 64
#define BN 64
#define BK 32

__global__ __launch_bounds__(256) void xproj_kernel(
    const float* __restrict__ x,
    const float* __restrict__ Wih,
    const float* __restrict__ bih,
    const float* __restrict__ bhh)
{
    __shared__ float As[BK][BM];
    __shared__ float Bs[BK][BN];

    const int tid  = threadIdx.x;
    const int mblk = blockIdx.x;
    const int nblk = blockIdx.y;

    const float* Arow = x   + (size_t)mblk * BM * IDIM;
    const float* Brow = Wih + (size_t)nblk * BN * IDIM;

    const int tx = tid & 15;
    const int ty = tid >> 4;

    float acc[4][4] = {};

    const int lr  = tid >> 2;
    const int lkq = (tid & 3) * 8;

    for (int k0 = 0; k0 < IDIM; k0 += BK) {
        {
            float4 v0 = *(const float4*)(Arow + lr * IDIM + k0 + lkq);
            float4 v1 = *(const float4*)(Arow + lr * IDIM + k0 + lkq + 4);
            As[lkq + 0][lr] = v0.x; As[lkq + 1][lr] = v0.y;
            As[lkq + 2][lr] = v0.z; As[lkq + 3][lr] = v0.w;
            As[lkq + 4][lr] = v1.x; As[lkq + 5][lr] = v1.y;
            As[lkq + 6][lr] = v1.z; As[lkq + 7][lr] = v1.w;

            float4 w0 = *(const float4*)(Brow + lr * IDIM + k0 + lkq);
            float4 w1 = *(const float4*)(Brow + lr * IDIM + k0 + lkq + 4);
            Bs[lkq + 0][lr] = w0.x; Bs[lkq + 1][lr] = w0.y;
            Bs[lkq + 2][lr] = w0.z; Bs[lkq + 3][lr] = w0.w;
            Bs[lkq + 4][lr] = w1.x; Bs[lkq + 5][lr] = w1.y;
            Bs[lkq + 6][lr] = w1.z; Bs[lkq + 7][lr] = w1.w;
        }
        __syncthreads();

        #pragma unroll
        for (int kk = 0; kk < BK; kk++) {
            float4 av = *(const float4*)&As[kk][ty * 4];
            float4 bv = *(const float4*)&Bs[kk][tx * 4];
            float a[4] = {av.x, av.y, av.z, av.w};
            float b[4] = {bv.x, bv.y, bv.z, bv.w};
            #pragma unroll
            for (int i = 0; i < 4; i++)
                #pragma unroll
                for (int j = 0; j < 4; j++)
                    acc[i][j] = fmaf(a[i], b[j], acc[i][j]);
        }
        __syncthreads();
    }

    const int mb = mblk * BM + ty * 4;
    const int nb = nblk * BN + tx * 4;
    float bias[4];
    #pragma unroll
    for (int j = 0; j < 4; j++)
        bias[j] = bih[nb + j] + bhh[nb + j];

    #pragma unroll
    for (int i = 0; i < 4; i++) {
        float4 v;
        v.x = acc[i][0] + bias[0];
        v.y = acc[i][1] + bias[1];
        v.z = acc[i][2] + bias[2];
        v.w = acc[i][3] + bias[3];
        *(float4*)&g_xg[(size_t)(mb + i) * G4 + nb] = v;
    }
}

// ---------------------------------------------------------------------------
// Kernel 2: recurrence. 16 clusters x 8 CTAs; cluster owns 2 batches; CTA
// rank owns 32 hidden units (128 gate rows). 512 threads (16 warps):
//   warp w: kseg = w>>2 (64-wide K segment), row group = w&3
//   thread: 1 gate row x 2 batches over its 64-K segment, W in 64 registers.
// Per step: k-loop (FMA floor ~1024cyc, 4 warps/SMSP hide latency) ->
// one __syncthreads -> 64 state-owner threads fuse (reduce + xg + activations
// + ys store + DSMEM h broadcast) -> one cluster barrier.
// ---------------------------------------------------------------------------
__global__ void __cluster_dims__(8, 1, 1) __launch_bounds__(512, 1)
lstm_rec_kernel(const float* __restrict__ Whh,
                const float* __restrict__ h0,
                const float* __restrict__ c0,
                float* __restrict__ out)
{
    __shared__ float h_s[2][2][HDIM];      // [buf][local batch][k]
    __shared__ float red_s[4][2][128];     // [kseg][local batch][local row]

    const int tid  = threadIdx.x;
    const int lane = tid & 31;
    const int wid  = tid >> 5;
    const int kseg = wid >> 2;             // 0..3
    const int lr   = (wid & 3) * 32 + lane; // 0..127 local gate row

    unsigned rank;
    asm("mov.u32 %0, %%cluster_ctarank;" : "=r"(rank));
    const int cl = blockIdx.x >> 3;
    const int b0 = cl * 2;

    // global W_hh row for this thread's gate row
    const int R = ((lr >> 5) << 8) + (int)rank * 32 + (lr & 31);

    // ---- preload W_hh slice: 64 floats/thread ----
    float wreg[64];
    {
        const float* W = Whh + (size_t)R * HDIM + kseg * 64;
        #pragma unroll
        for (int i = 0; i < 16; i++) {
            float4 v = *(const float4*)(W + 4 * i);
            wreg[4*i+0] = v.x; wreg[4*i+1] = v.y;
            wreg[4*i+2] = v.z; wreg[4*i+3] = v.w;
        }
    }

    // ---- init h_s[0] with h0 ----
    for (int i = tid; i < 2 * HDIM; i += 512)
        h_s[0][i >> 8][i & 255] = h0[(size_t)(b0 + (i >> 8)) * HDIM + (i & 255)];

    // ---- state-owner threads: tid<64 -> (bb = wid, j = lane) ----
    const int bb = wid & 1;
    const int j  = lane;
    float c_reg = 0.f, h_last = 0.f;
    uint32_t law0 = 0, law1 = 0;
    if (tid < 64) {
        c_reg = c0[(size_t)(b0 + bb) * HDIM + (int)rank * 32 + j];
        law0 = (uint32_t)__cvta_generic_to_shared(&h_s[0][bb][(int)rank * 32 + j]);
        law1 = (uint32_t)__cvta_generic_to_shared(&h_s[1][bb][(int)rank * 32 + j]);
    }
    __syncthreads();

    auto step = [&](int t, const float (*h_rd)[HDIM], uint32_t law) {
        // prefetch xg for the 4 gates (consumed after the k-loop)
        float xg0 = 0.f, xg1 = 0.f, xg2 = 0.f, xg3 = 0.f;
        if (tid < 64) {
            const float* xp = g_xg + ((size_t)t * BATCH + b0 + bb) * G4
                                   + (int)rank * 32 + j;
            xg0 = __ldg(xp);
            xg1 = __ldg(xp + 256);
            xg2 = __ldg(xp + 512);
            xg3 = __ldg(xp + 768);
        }

        // k-loop: 64 K, 1 row x 2 batches, warp-uniform broadcast LDS
        float a0 = 0.f, a1 = 0.f;
        const float* hp0 = &h_rd[0][kseg * 64];
        const float* hp1 = &h_rd[1][kseg * 64];
        #pragma unroll
        for (int i = 0; i < 64; i += 4) {
            float4 u = *(const float4*)(hp0 + i);
            float4 v = *(const float4*)(hp1 + i);
            a0 = fmaf(wreg[i+0], u.x, a0); a1 = fmaf(wreg[i+0], v.x, a1);
            a0 = fmaf(wreg[i+1], u.y, a0); a1 = fmaf(wreg[i+1], v.y, a1);
            a0 = fmaf(wreg[i+2], u.z, a0); a1 = fmaf(wreg[i+2], v.z, a1);
            a0 = fmaf(wreg[i+3], u.w, a0); a1 = fmaf(wreg[i+3], v.w, a1);
        }
        red_s[kseg][0][lr] = a0;
        red_s[kseg][1][lr] = a1;
        __syncthreads();

        // fused reduce + activations + state update + broadcast
        if (tid < 64) {
            float s0 = xg0, s1 = xg1, s2 = xg2, s3 = xg3;
            #pragma unroll
            for (int ks = 0; ks < 4; ks++) {
                s0 += red_s[ks][bb][ 0 + j];
                s1 += red_s[ks][bb][32 + j];
                s2 += red_s[ks][bb][64 + j];
                s3 += red_s[ks][bb][96 + j];
            }
            const float ig = 1.f / (1.f + __expf(-s0));
            const float fg = 1.f / (1.f + __expf(-s1));
            const float gt = tanhf(s2);
            const float og = 1.f / (1.f + __expf(-s3));

            c_reg = fg * c_reg + ig * gt;
            const float h = og * tanhf(c_reg);
            h_last = h;

            out[((size_t)t * BATCH + b0 + bb) * HDIM + (int)rank * 32 + j] = h;

            #pragma unroll
            for (int r = 0; r < 8; r++) {
                uint32_t raddr;
                asm volatile("mapa.shared::cluster.u32 %0, %1, %2;"
                             : "=r"(raddr) : "r"(law), "r"(r));
                asm volatile("st.shared::cluster.f32 [%0], %1;"
                             :: "r"(raddr), "f"(h) : "memory");
            }
        }

        // one cluster barrier per step (release of DSMEM writes / acquire)
        asm volatile("barrier.cluster.arrive.aligned;" ::: "memory");
        asm volatile("barrier.cluster.wait.aligned;" ::: "memory");
    };

    // t-loop unrolled by 2: fixed compile-time buffer roles
    for (int t = SEQ - 1; t > 0; t -= 2) {
        step(t,     h_s[0], law1);   // read buf0, write buf1
        step(t - 1, h_s[1], law0);   // read buf1, write buf0
    }

    if (tid < 64) {
        float* hT = out + (size_t)SEQ * BATCH * HDIM;
        float* cT = hT + (size_t)BATCH * HDIM;
        hT[(size_t)(b0 + bb) * HDIM + (int)rank * 32 + j] = h_last;
        cT[(size_t)(b0 + bb) * HDIM + (int)rank * 32 + j] = c_reg;
    }
}

// ---------------------------------------------------------------------------
extern "C" void kernel_launch(void* const* d_in, const int* in_sizes, int n_in,
                              void* d_out, int out_size)
{
    (void)in_sizes; (void)n_in; (void)out_size;
    const float* x   = (const float*)d_in[0];
    const float* h0  = (const float*)d_in[1];
    const float* c0  = (const float*)d_in[2];
    const float* Wih = (const float*)d_in[3];
    const float* Whh = (const float*)d_in[4];
    const float* bih = (const float*)d_in[5];
    const float* bhh = (const float*)d_in[6];
    float* out = (float*)d_out;

    dim3 gridP(65536 / BM, G4 / BN);   // (1024, 16)
    xproj_kernel<<<gridP, 256>>>(x, Wih, bih, bhh);

    lstm_rec_kernel<<<128, 512>>>(Whh, h0, c0, out);
}

// round 4
// speedup vs baseline: 1.6483x; 1.4308x over previous
#include <cuda_runtime.h>
#include <cstdint>

#define SEQ   2048
#define BATCH 32
#define IDIM  256
#define HDIM  256
#define G4    1024   // 4*HDIM gate rows

// 268 MB scratch for precomputed input projections: Xg[t][b][g]
__device__ float g_xg[SEQ * BATCH * G4];

// ---------------------------------------------------------------------------
// Kernel 1 (unchanged control): Xg = x @ W_ih^T + b_ih + b_hh
// ---------------------------------------------------------------------------
#define BM 64
#define BN 64
#define BK 32

__global__ __launch_bounds__(256) void xproj_kernel(
    const float* __restrict__ x,
    const float* __restrict__ Wih,
    const float* __restrict__ bih,
    const float* __restrict__ bhh)
{
    __shared__ float As[BK][BM];
    __shared__ float Bs[BK][BN];

    const int tid  = threadIdx.x;
    const int mblk = blockIdx.x;
    const int nblk = blockIdx.y;

    const float* Arow = x   + (size_t)mblk * BM * IDIM;
    const float* Brow = Wih + (size_t)nblk * BN * IDIM;

    const int tx = tid & 15;
    const int ty = tid >> 4;

    float acc[4][4] = {};

    const int lr  = tid >> 2;
    const int lkq = (tid & 3) * 8;

    for (int k0 = 0; k0 < IDIM; k0 += BK) {
        {
            float4 v0 = *(const float4*)(Arow + lr * IDIM + k0 + lkq);
            float4 v1 = *(const float4*)(Arow + lr * IDIM + k0 + lkq + 4);
            As[lkq + 0][lr] = v0.x; As[lkq + 1][lr] = v0.y;
            As[lkq + 2][lr] = v0.z; As[lkq + 3][lr] = v0.w;
            As[lkq + 4][lr] = v1.x; As[lkq + 5][lr] = v1.y;
            As[lkq + 6][lr] = v1.z; As[lkq + 7][lr] = v1.w;

            float4 w0 = *(const float4*)(Brow + lr * IDIM + k0 + lkq);
            float4 w1 = *(const float4*)(Brow + lr * IDIM + k0 + lkq + 4);
            Bs[lkq + 0][lr] = w0.x; Bs[lkq + 1][lr] = w0.y;
            Bs[lkq + 2][lr] = w0.z; Bs[lkq + 3][lr] = w0.w;
            Bs[lkq + 4][lr] = w1.x; Bs[lkq + 5][lr] = w1.y;
            Bs[lkq + 6][lr] = w1.z; Bs[lkq + 7][lr] = w1.w;
        }
        __syncthreads();

        #pragma unroll
        for (int kk = 0; kk < BK; kk++) {
            float4 av = *(const float4*)&As[kk][ty * 4];
            float4 bv = *(const float4*)&Bs[kk][tx * 4];
            float a[4] = {av.x, av.y, av.z, av.w};
            float b[4] = {bv.x, bv.y, bv.z, bv.w};
            #pragma unroll
            for (int i = 0; i < 4; i++)
                #pragma unroll
                for (int jj = 0; jj < 4; jj++)
                    acc[i][jj] = fmaf(a[i], b[jj], acc[i][jj]);
        }
        __syncthreads();
    }

    const int mb = mblk * BM + ty * 4;
    const int nb = nblk * BN + tx * 4;
    float bias[4];
    #pragma unroll
    for (int jj = 0; jj < 4; jj++)
        bias[jj] = bih[nb + jj] + bhh[nb + jj];

    #pragma unroll
    for (int i = 0; i < 4; i++) {
        float4 v;
        v.x = acc[i][0] + bias[0];
        v.y = acc[i][1] + bias[1];
        v.z = acc[i][2] + bias[2];
        v.w = acc[i][3] + bias[3];
        *(float4*)&g_xg[(size_t)(mb + i) * G4 + nb] = v;
    }
}

// ---------------------------------------------------------------------------
// Kernel 2: recurrence with FFMA2 k-loop + mbarrier/st.async cluster sync.
// 16 clusters x 8 CTAs; cluster owns 2 batches; CTA rank owns 32 hidden units
// (128 gate rows). 512 threads: warp w -> kseg=w>>2 (64-wide K segment),
// thread handles 1 gate row x 2 batches with packed-pair weights in 32 u64.
// ---------------------------------------------------------------------------
__device__ __forceinline__ void ffma2(uint64_t& acc, uint64_t a, uint64_t b) {
    asm("fma.rn.f32x2 %0, %1, %2, %0;" : "+l"(acc) : "l"(a), "l"(b));
}

__device__ __forceinline__ void mbar_wait(uint32_t addr, unsigned par) {
    asm volatile(
        "{\n\t"
        ".reg .pred P;\n\t"
        "WAIT_%=:\n\t"
        "mbarrier.try_wait.parity.acquire.cta.shared::cta.b64 P, [%0], %1, 0x989680;\n\t"
        "@P bra DONE_%=;\n\t"
        "bra WAIT_%=;\n\t"
        "DONE_%=:\n\t"
        "}"
        :: "r"(addr), "r"(par) : "memory");
}

__global__ void __cluster_dims__(8, 1, 1) __launch_bounds__(512, 1)
lstm_rec_kernel(const float* __restrict__ Whh,
                const float* __restrict__ h0,
                const float* __restrict__ c0,
                float* __restrict__ out)
{
    __shared__ float h_s[2][2][HDIM];        // [buf][local batch][k]
    __shared__ float red_s[4][2][128];       // [kseg][local batch][local row]
    __shared__ alignas(8) unsigned long long mbar[2];  // full-barrier per buf

    const int tid  = threadIdx.x;
    const int lane = tid & 31;
    const int wid  = tid >> 5;
    const int kseg = wid >> 2;
    const int lr   = (wid & 3) * 32 + lane;

    unsigned rank;
    asm("mov.u32 %0, %%cluster_ctarank;" : "=r"(rank));
    const int b0 = (blockIdx.x >> 3) * 2;
    const int R  = ((lr >> 5) << 8) + (int)rank * 32 + (lr & 31);

    // ---- preload W_hh slice, packed into 32 x u64 pairs ----
    uint64_t wp[32];
    {
        const float* W = Whh + (size_t)R * HDIM + kseg * 64;
        #pragma unroll
        for (int i = 0; i < 16; i++) {
            float4 v = *(const float4*)(W + 4 * i);
            asm("mov.b64 %0, {%1,%2};" : "=l"(wp[2*i+0]) : "f"(v.x), "f"(v.y));
            asm("mov.b64 %0, {%1,%2};" : "=l"(wp[2*i+1]) : "f"(v.z), "f"(v.w));
        }
    }

    // ---- init h_s[0] with h0 ----
    for (int i = tid; i < 2 * HDIM; i += 512)
        h_s[0][i >> 8][i & 255] = h0[(size_t)(b0 + (i >> 8)) * HDIM + (i & 255)];

    // ---- owners (tid < 64): (bb, j) state cell ----
    const int bb = wid & 1;
    const int j  = lane;
    float c_reg = 0.f, h_last = 0.f;
    if (tid < 64)
        c_reg = c0[(size_t)(b0 + bb) * HDIM + (int)rank * 32 + j];

    const uint32_t mb_addr = (uint32_t)__cvta_generic_to_shared(&mbar[0]);
    if (tid == 0) {
        asm volatile("mbarrier.init.shared.b64 [%0], %1;" :: "r"(mb_addr), "r"(1) : "memory");
        asm volatile("mbarrier.init.shared.b64 [%0], %1;" :: "r"(mb_addr + 8), "r"(1) : "memory");
        // arm both buffers for their first fill (2048 B = 512 floats each)
        asm volatile("mbarrier.arrive.expect_tx.shared.b64 _, [%0], %1;" :: "r"(mb_addr), "r"(2048) : "memory");
        asm volatile("mbarrier.arrive.expect_tx.shared.b64 _, [%0], %1;" :: "r"(mb_addr + 8), "r"(2048) : "memory");
    }
    __syncthreads();
    // one-time cluster barrier: all mbarriers live before any remote st.async
    asm volatile("barrier.cluster.arrive.aligned;" ::: "memory");
    asm volatile("barrier.cluster.wait.aligned;" ::: "memory");

    const uint32_t h_base = (uint32_t)__cvta_generic_to_shared(&h_s[0][0][0]);
    const uint32_t ksoff  = (uint32_t)(kseg * 64 * 4);

    auto step = [&](int t, int rd, bool dowait, unsigned par, bool dostore) {
        // xg prefetch first: DRAM latency overlaps the wait + k-loop
        float xg0 = 0.f, xg1 = 0.f, xg2 = 0.f, xg3 = 0.f;
        if (tid < 64) {
            const float* xp = g_xg + ((size_t)t * BATCH + b0 + bb) * G4
                                   + (int)rank * 32 + j;
            xg0 = __ldg(xp);
            xg1 = __ldg(xp + 256);
            xg2 = __ldg(xp + 512);
            xg3 = __ldg(xp + 768);
        }

        const uint32_t mb_rd = mb_addr + (uint32_t)rd * 8;
        if (dowait) {
            mbar_wait(mb_rd, par);
            if (tid == 0)  // re-arm for this buffer's next fill
                asm volatile("mbarrier.arrive.expect_tx.shared.b64 _, [%0], %1;"
                             :: "r"(mb_rd), "r"(2048) : "memory");
        }

        // ---- k-loop: packed f32x2 FMAs, warp-uniform broadcast LDS ----
        const uint32_t a0 = h_base + (uint32_t)rd * (2 * HDIM * 4) + ksoff;
        const uint32_t a1 = a0 + HDIM * 4;
        uint64_t acc0 = 0ull, acc1 = 0ull;
        #pragma unroll
        for (int i = 0; i < 64; i += 4) {
            uint64_t u01, u23, v01, v23;
            asm volatile("ld.shared.v2.u64 {%0,%1}, [%2];"
                         : "=l"(u01), "=l"(u23) : "r"(a0 + i * 4));
            asm volatile("ld.shared.v2.u64 {%0,%1}, [%2];"
                         : "=l"(v01), "=l"(v23) : "r"(a1 + i * 4));
            ffma2(acc0, wp[i / 2 + 0], u01);
            ffma2(acc1, wp[i / 2 + 0], v01);
            ffma2(acc0, wp[i / 2 + 1], u23);
            ffma2(acc1, wp[i / 2 + 1], v23);
        }
        {
            uint32_t lo, hi;
            asm("mov.b64 {%0,%1}, %2;" : "=r"(lo), "=r"(hi) : "l"(acc0));
            red_s[kseg][0][lr] = __uint_as_float(lo) + __uint_as_float(hi);
            asm("mov.b64 {%0,%1}, %2;" : "=r"(lo), "=r"(hi) : "l"(acc1));
            red_s[kseg][1][lr] = __uint_as_float(lo) + __uint_as_float(hi);
        }
        __syncthreads();   // also orders: all reads of h_s[rd] done before stores below

        // ---- owners: reduce + activations + state + broadcast ----
        if (tid < 64) {
            float s0 = xg0, s1 = xg1, s2 = xg2, s3 = xg3;
            #pragma unroll
            for (int ks = 0; ks < 4; ks++) {
                s0 += red_s[ks][bb][ 0 + j];
                s1 += red_s[ks][bb][32 + j];
                s2 += red_s[ks][bb][64 + j];
                s3 += red_s[ks][bb][96 + j];
            }
            const float ig = __fdividef(1.f, 1.f + __expf(-s0));
            const float fg = __fdividef(1.f, 1.f + __expf(-s1));
            const float gt = tanhf(s2);
            const float og = __fdividef(1.f, 1.f + __expf(-s3));

            c_reg = fg * c_reg + ig * gt;
            const float h = og * tanhf(c_reg);
            h_last = h;

            out[((size_t)t * BATCH + b0 + bb) * HDIM + (int)rank * 32 + j] = h;

            if (dostore) {
                const int wr = rd ^ 1;
                const uint32_t lh = h_base + (uint32_t)wr * (2 * HDIM * 4)
                                  + (uint32_t)bb * (HDIM * 4)
                                  + (uint32_t)((int)rank * 32 + j) * 4;
                const uint32_t lm = mb_addr + (uint32_t)wr * 8;
                const uint32_t hv = __float_as_uint(h);
                #pragma unroll
                for (int r = 0; r < 8; r++) {
                    uint32_t rh, rm;
                    asm volatile("mapa.shared::cluster.u32 %0, %1, %2;"
                                 : "=r"(rh) : "r"(lh), "r"(r));
                    asm volatile("mapa.shared::cluster.u32 %0, %1, %2;"
                                 : "=r"(rm) : "r"(lm), "r"(r));
                    asm volatile(
                        "st.async.shared::cluster.mbarrier::complete_tx::bytes.b32 [%0], %1, [%2];"
                        :: "r"(rh), "r"(hv), "r"(rm) : "memory");
                }
            }
        }
        // no trailing barrier: next step's mbarrier wait provides the sync
    };

    unsigned par0 = 0, par1 = 0;
    step(SEQ - 1, 0, false, 0, true);              // s=0: buf0 local, write buf1
    for (int t = SEQ - 2; t >= 1; t -= 2) {
        step(t,     1, true, par1, true); par1 ^= 1;
        step(t - 1, 0, true, par0, true); par0 ^= 1;
    }
    step(0, 1, true, par1, false);                 // final: no broadcast

    if (tid < 64) {
        float* hT = out + (size_t)SEQ * BATCH * HDIM;
        float* cT = hT + (size_t)BATCH * HDIM;
        hT[(size_t)(b0 + bb) * HDIM + (int)rank * 32 + j] = h_last;
        cT[(size_t)(b0 + bb) * HDIM + (int)rank * 32 + j] = c_reg;
    }
}

// ---------------------------------------------------------------------------
extern "C" void kernel_launch(void* const* d_in, const int* in_sizes, int n_in,
                              void* d_out, int out_size)
{
    (void)in_sizes; (void)n_in; (void)out_size;
    const float* x   = (const float*)d_in[0];
    const float* h0  = (const float*)d_in[1];
    const float* c0  = (const float*)d_in[2];
    const float* Wih = (const float*)d_in[3];
    const float* Whh = (const float*)d_in[4];
    const float* bih = (const float*)d_in[5];
    const float* bhh = (const float*)d_in[6];
    float* out = (float*)d_out;

    dim3 gridP(65536 / BM, G4 / BN);   // (1024, 16)
    xproj_kernel<<<gridP, 256>>>(x, Wih, bih, bhh);

    lstm_rec_kernel<<<128, 512>>>(Whh, h0, c0, out);
}